// round 1
// baseline (speedup 1.0000x reference)
#include <cuda_runtime.h>
#include <cuda_bf16.h>

#define BATCH 8
#define SEQT 4096
#define DMODEL 512
#define NHEADS 8
#define CHEAD 64
#define TD3 1536      // 3*D
#define NF 576        // 9*C

// ---------------- scratch (device globals; allocation-free) ----------------
__device__ float g_qkv[(long)BATCH * SEQT * TD3];   // 201 MB
__device__ float g_qdw[(long)BATCH * SEQT * TD3];   // 201 MB (post depthwise)
__device__ float g_f[(long)BATCH * SEQT * NF];      // 75 MB
__device__ float g_nrm[BATCH * 1024];               // q norms [0..511], k norms [512..1023]
__device__ float g_attn[BATCH * NHEADS * CHEAD * CHEAD];

// ---------------- K1: qkv = x @ W_qkv  (M=32768,K=512,N=1536) ----------------
#define BM 128
#define BN 128
#define BK 16
#define TM 8
#define TN 8

__global__ __launch_bounds__(256) void sgemm_k(const float* __restrict__ A,
                                               const float* __restrict__ Bm) {
    __shared__ float As[BK][BM];
    __shared__ float Bs[BK][BN];
    const int M = BATCH * SEQT, N = TD3, K = DMODEL;
    int bx = blockIdx.x;          // N tile
    int by = blockIdx.y;          // M tile
    int tid = threadIdx.x;
    int tRow = tid / (BN / TN);   // 0..15
    int tCol = tid % (BN / TN);   // 0..15
    const float* Ab = A + (long)by * BM * K;
    const float* Bb = Bm + bx * BN;
    float acc[TM][TN] = {};
    int aRow = tid >> 2;          // 0..63
    int aCol = (tid & 3) * 4;     // 0,4,8,12
    int bRow = tid >> 5;          // 0..7
    int bCol = (tid & 31) * 4;    // 0..124

    for (int k0 = 0; k0 < K; k0 += BK) {
#pragma unroll
        for (int i = 0; i < 2; i++) {
            int r = aRow + i * 64;
            float4 v = *(const float4*)(Ab + (long)r * K + k0 + aCol);
            As[aCol + 0][r] = v.x; As[aCol + 1][r] = v.y;
            As[aCol + 2][r] = v.z; As[aCol + 3][r] = v.w;
        }
#pragma unroll
        for (int i = 0; i < 2; i++) {
            int r = bRow + i * 8;
            float4 v = *(const float4*)(Bb + (long)(k0 + r) * N + bCol);
            *(float4*)&Bs[r][bCol] = v;
        }
        __syncthreads();
#pragma unroll
        for (int k = 0; k < BK; k++) {
            float ra[TM], rb[TN];
#pragma unroll
            for (int i = 0; i < TM; i++) ra[i] = As[k][tRow * TM + i];
#pragma unroll
            for (int j = 0; j < TN; j++) rb[j] = Bs[k][tCol * TN + j];
#pragma unroll
            for (int i = 0; i < TM; i++)
#pragma unroll
                for (int j = 0; j < TN; j++) acc[i][j] += ra[i] * rb[j];
        }
        __syncthreads();
    }
    float* Cb = g_qkv + (long)by * BM * N + bx * BN;
#pragma unroll
    for (int i = 0; i < TM; i++)
#pragma unroll
        for (int j = 0; j < TN; j += 4) {
            float4 v = {acc[i][j], acc[i][j + 1], acc[i][j + 2], acc[i][j + 3]};
            *(float4*)(Cb + (long)(tRow * TM + i) * N + tCol * TN + j) = v;
        }
}

// ---------------- K2: depthwise k=3 over T on qkv ----------------
__global__ void dw3_k(const float* __restrict__ w) {
    int idx = blockIdx.x * blockDim.x + threadIdx.x;  // B*T*1536 = 50.3M < 2^31
    int ch = idx % TD3;
    int bt = idx / TD3;
    int t = bt % SEQT;
    const float* base = g_qkv + idx;
    float w0 = w[ch * 3], w1 = w[ch * 3 + 1], w2 = w[ch * 3 + 2];
    float acc = w1 * base[0];
    if (t > 0)        acc += w0 * base[-TD3];
    if (t < SEQT - 1) acc += w2 * base[TD3];
    g_qdw[idx] = acc;
}

// ---------------- K3: fc over 3H axis -> f (B,T,9,C) ----------------
__global__ __launch_bounds__(256) void fc_k(const float* __restrict__ Wfc,
                                            const float* __restrict__ bfc) {
    __shared__ float s[4][TD3];
    __shared__ float w[24 * 9];
    __shared__ float bb[9];
    int bt0 = blockIdx.x * 4;
    int tid = threadIdx.x;
    if (tid < 216) w[tid] = Wfc[tid];
    if (tid < 9) bb[tid] = bfc[tid];
    const float* src = g_qdw + (long)bt0 * TD3;
    for (int i = tid; i < 4 * TD3; i += 256) s[i / TD3][i % TD3] = src[i];
    __syncthreads();
    for (int o = tid; o < 4 * NF; o += 256) {
        int tt = o / NF, nc = o % NF;
        int n = nc / CHEAD, c = nc % CHEAD;
        float acc = bb[n];
#pragma unroll
        for (int h = 0; h < 24; h++) acc += s[tt][h * CHEAD + c] * w[h * 9 + n];
        g_f[(long)(bt0 + tt) * NF + nc] = acc;
    }
}

// ---------------- K4: q/k L2 norms over T ----------------
__global__ __launch_bounds__(256) void norm_k() {
    int b = blockIdx.x >> 4;
    int ct = blockIdx.x & 15;
    int lc = threadIdx.x & 63;
    int tl = threadIdx.x >> 6;        // 0..3
    int ch = ct * 64 + lc;            // 0..1023
    const float* p = g_qdw + (long)b * SEQT * TD3 + ch;
    float acc = 0.f;
    for (int t = tl; t < SEQT; t += 4) {
        float v = p[(long)t * TD3];
        acc += v * v;
    }
    __shared__ float sm[256];
    sm[threadIdx.x] = acc;
    __syncthreads();
    if (tl == 0) {
        float s = sm[lc] + sm[lc + 64] + sm[lc + 128] + sm[lc + 192];
        g_nrm[b * 1024 + ch] = fmaxf(sqrtf(s), 1e-12f);
    }
}

// ---------------- K5: attention scores + softmax ----------------
__global__ __launch_bounds__(256) void attn_k(const float* __restrict__ temp) {
    int b = blockIdx.x >> 3;
    int h = blockIdx.x & 7;
    const float* qbase = g_qdw + (long)b * SEQT * TD3 + h * CHEAD;
    const float* kbase = qbase + DMODEL;
    __shared__ float qs[16][64], ks[16][64];
    __shared__ float S[64][65];
    int tid = threadIdx.x;
    int cy = tid >> 4, dx = tid & 15;
    float acc[4][4] = {};
    for (int t0 = 0; t0 < SEQT; t0 += 16) {
        for (int i = tid; i < 1024; i += 256) {
            int tt = i >> 6, cc = i & 63;
            long off = (long)(t0 + tt) * TD3 + cc;
            qs[tt][cc] = qbase[off];
            ks[tt][cc] = kbase[off];
        }
        __syncthreads();
#pragma unroll
        for (int tt = 0; tt < 16; tt++) {
            float ra[4], rb[4];
#pragma unroll
            for (int i = 0; i < 4; i++) ra[i] = qs[tt][cy * 4 + i];
#pragma unroll
            for (int j = 0; j < 4; j++) rb[j] = ks[tt][dx * 4 + j];
#pragma unroll
            for (int i = 0; i < 4; i++)
#pragma unroll
                for (int j = 0; j < 4; j++) acc[i][j] += ra[i] * rb[j];
        }
        __syncthreads();
    }
    const float* nq = g_nrm + b * 1024 + h * CHEAD;
    const float* nk = nq + DMODEL;
    float tmpr = temp[h];
#pragma unroll
    for (int i = 0; i < 4; i++)
#pragma unroll
        for (int j = 0; j < 4; j++)
            S[cy * 4 + i][dx * 4 + j] =
                acc[i][j] / (nq[cy * 4 + i] * nk[dx * 4 + j]) * tmpr;
    __syncthreads();
    if (tid < 64) {
        float m = -1e30f;
        for (int d = 0; d < 64; d++) m = fmaxf(m, S[tid][d]);
        float s = 0.f;
        for (int d = 0; d < 64; d++) {
            float e = expf(S[tid][d] - m);
            S[tid][d] = e;
            s += e;
        }
        float inv = 1.f / s;
        float* dst = g_attn + ((blockIdx.x) * 64 + tid) * 64;
        for (int d = 0; d < 64; d++) dst[d] = S[tid][d] * inv;
    }
}

// ---------------- K6: regional context (k3 -> relu -> k5), writes out ----------------
__global__ void ctx_k(const float* __restrict__ x, const float* __restrict__ w1,
                      const float* __restrict__ w2, float* __restrict__ out) {
    int idx = blockIdx.x * blockDim.x + threadIdx.x;   // B*T*512 = 16.7M
    int d = idx % DMODEL;
    int bt = idx / DMODEL;
    int t = bt % SEQT;
    float a0 = w1[d * 3], a1 = w1[d * 3 + 1], a2 = w1[d * 3 + 2];
    const float* xb = x + idx;
    float r[5];
#pragma unroll
    for (int j = 0; j < 5; j++) {
        int tp = t + j - 2;
        float v = 0.f;
        if (tp >= 0 && tp < SEQT) {
            float xm = (tp > 0) ? xb[(j - 3) * DMODEL] : 0.f;
            float xc = xb[(j - 2) * DMODEL];
            float xp = (tp < SEQT - 1) ? xb[(j - 1) * DMODEL] : 0.f;
            v = fmaxf(a0 * xm + a1 * xc + a2 * xp, 0.f);
        }
        r[j] = v;
    }
    const float* b2 = w2 + d * 5;
    float acc = 0.f;
#pragma unroll
    for (int j = 0; j < 5; j++) acc += b2[j] * r[j];
    out[idx] = acc;
}

// ---------------- K7: grouped conv (fc branch), += out ----------------
__global__ void gconv_k(const float* __restrict__ wd, const float* __restrict__ bd,
                        float* __restrict__ out) {
    int idx = blockIdx.x * blockDim.x + threadIdx.x;   // B*T*512
    int d = idx % DMODEL;
    int bt = idx / DMODEL;
    int t = bt % SEQT;
    int g = d >> 3;                 // 8 out channels per group
    const float* wp = wd + d * 27;
    const float* fb = g_f + (long)bt * NF + g * 9;
    float acc = bd[d];
#pragma unroll
    for (int i = 0; i < 9; i++) {
        float w0 = wp[i * 3], w1 = wp[i * 3 + 1], w2 = wp[i * 3 + 2];
        acc += w1 * fb[i];
        if (t > 0)        acc += w0 * fb[i - NF];
        if (t < SEQT - 1) acc += w2 * fb[i + NF];
    }
    out[idx] += acc;
}

// ---------------- K8: out_att = attn @ V, += out ----------------
__global__ __launch_bounds__(256) void outatt_k(float* __restrict__ out) {
    int tt = blockIdx.x & 63;         // T tile of 64
    int bh = blockIdx.x >> 6;
    int h = bh & 7, b = bh >> 3;
    __shared__ float A[64][65];
    __shared__ float vs[4][64];
    int tid = threadIdx.x;
    const float* asrc = g_attn + bh * 4096;
    for (int i = tid; i < 4096; i += 256) A[i >> 6][i & 63] = asrc[i];
    int c = tid & 63, tl = tid >> 6;
    int t0 = tt * 64;
    const float* vbase = g_qdw + (long)b * SEQT * TD3 + 2 * DMODEL + h * CHEAD;
    float* obase = out + ((long)b * SEQT + t0) * DMODEL + h * CHEAD;
    __syncthreads();
    for (int ts = 0; ts < 64; ts += 4) {
        vs[tl][c] = vbase[(long)(t0 + ts + tl) * TD3 + c];
        __syncthreads();
        float acc = 0.f;
#pragma unroll
        for (int d = 0; d < 64; d++) acc += A[c][d] * vs[tl][d];
        obase[(long)(ts + tl) * DMODEL + c] += acc;
        __syncthreads();
    }
}

// ---------------- launch ----------------
extern "C" void kernel_launch(void* const* d_in, const int* in_sizes, int n_in,
                              void* d_out, int out_size) {
    const float* x       = (const float*)d_in[0];
    const float* W_qkv   = (const float*)d_in[1];
    const float* w_qkvdw = (const float*)d_in[2];
    const float* w_ctx1  = (const float*)d_in[3];
    const float* w_ctx2  = (const float*)d_in[4];
    const float* W_fc    = (const float*)d_in[5];
    const float* b_fc    = (const float*)d_in[6];
    const float* w_dep   = (const float*)d_in[7];
    const float* b_dep   = (const float*)d_in[8];
    const float* temp    = (const float*)d_in[9];
    float* out = (float*)d_out;

    // 1. qkv GEMM
    sgemm_k<<<dim3(TD3 / BN, (BATCH * SEQT) / BM), 256>>>(x, W_qkv);
    // 2. depthwise k=3
    dw3_k<<<(BATCH * SEQT * TD3) / 256, 256>>>(w_qkvdw);
    // 3. fc branch
    fc_k<<<(BATCH * SEQT) / 4, 256>>>(W_fc, b_fc);
    // 4. q/k norms
    norm_k<<<BATCH * 16, 256>>>();
    // 5. attention scores + softmax
    attn_k<<<BATCH * NHEADS, 256>>>(temp);
    // 6. ctx branch (writes out)
    ctx_k<<<(BATCH * SEQT * DMODEL) / 256, 256>>>(x, w_ctx1, w_ctx2, out);
    // 7. grouped conv (+= out)
    gconv_k<<<(BATCH * SEQT * DMODEL) / 256, 256>>>(w_dep, b_dep, out);
    // 8. attn @ V (+= out)
    outatt_k<<<BATCH * NHEADS * (SEQT / 64), 256>>>(out);
}

// round 2
// speedup vs baseline: 1.8837x; 1.8837x over previous
#include <cuda_runtime.h>
#include <cuda_bf16.h>
#include <cstdint>

#define BATCH 8
#define SEQT 4096
#define DMODEL 512
#define NHEADS 8
#define CHEAD 64
#define TD3 1536      // 3*D
#define NF 576        // 9*C
#define MTOT (BATCH * SEQT)   // 32768

// ---------------- scratch (device globals; allocation-free) ----------------
__device__ float g_qkv[(long)MTOT * TD3];           // 201 MB (post-GEMM)
__device__ float g_qdw[(long)MTOT * TD3];           // 201 MB (post depthwise)
__device__ float g_f[(long)MTOT * NF];              // 75 MB
__device__ float g_attn[BATCH * NHEADS * CHEAD * CHEAD];
__device__ float g_part[BATCH * NHEADS * 8 * CHEAD * CHEAD];   // QK^T partials (8 t-segments)
__device__ float g_nrmp[BATCH * 16 * 1024];         // norm^2 partials (16 t-segments)
__device__ __nv_bfloat16 g_Ahi[(long)MTOT * DMODEL];
__device__ __nv_bfloat16 g_Alo[(long)MTOT * DMODEL];
__device__ __nv_bfloat16 g_WThi[TD3 * DMODEL];      // transposed W (N,K)
__device__ __nv_bfloat16 g_WTlo[TD3 * DMODEL];

// ---------------- convert x -> bf16 hi/lo ----------------
__global__ void convA_k(const float* __restrict__ x) {
    int i = blockIdx.x * blockDim.x + threadIdx.x;   // over float4s: 4.19M
    float4 v = ((const float4*)x)[i];
    float vv[4] = {v.x, v.y, v.z, v.w};
#pragma unroll
    for (int j = 0; j < 4; j++) {
        __nv_bfloat16 hi = __float2bfloat16_rn(vv[j]);
        __nv_bfloat16 lo = __float2bfloat16_rn(vv[j] - __bfloat162float(hi));
        g_Ahi[(long)i * 4 + j] = hi;
        g_Alo[(long)i * 4 + j] = lo;
    }
}

// ---------------- convert + transpose W -> bf16 hi/lo (N,K) ----------------
__global__ void convW_k(const float* __restrict__ W) {
    int i = blockIdx.x * blockDim.x + threadIdx.x;   // 786432
    int k = i / TD3, n = i % TD3;
    float v = W[i];
    __nv_bfloat16 hi = __float2bfloat16_rn(v);
    __nv_bfloat16 lo = __float2bfloat16_rn(v - __bfloat162float(hi));
    g_WThi[n * DMODEL + k] = hi;
    g_WTlo[n * DMODEL + k] = lo;
}

// ---------------- K1: bf16-split tensor-core GEMM ----------------
// C(32768,1536) = A(32768,512) * W(512,1536), via Ahi*Bhi + Ahi*Blo + Alo*Bhi
// CTA 128x128x32, 8 warps (2x4), warp tile 64x32, mma m16n8k16
#define SM_ABUF 5120      // elems per (buf,h) A plane: 128*40
#define SM_BBASE 20480    // B region start (elems)

__device__ __forceinline__ void ldsm4(uint32_t* r, uint32_t addr) {
    asm volatile("ldmatrix.sync.aligned.m8n8.x4.shared.b16 {%0,%1,%2,%3},[%4];\n"
                 : "=r"(r[0]), "=r"(r[1]), "=r"(r[2]), "=r"(r[3]) : "r"(addr));
}
#define MMA_BF16(c, A, B)                                                          \
    asm volatile(                                                                  \
        "mma.sync.aligned.m16n8k16.row.col.f32.bf16.bf16.f32 "                     \
        "{%0,%1,%2,%3},{%4,%5,%6,%7},{%8,%9},{%0,%1,%2,%3};\n"                     \
        : "+f"(c[0]), "+f"(c[1]), "+f"(c[2]), "+f"(c[3])                           \
        : "r"(A[0]), "r"(A[1]), "r"(A[2]), "r"(A[3]), "r"(B[0]), "r"(B[1]))

__global__ __launch_bounds__(256) void gemm_k() {
    extern __shared__ __align__(16) __nv_bfloat16 smem[];
    const int tid = threadIdx.x;
    const int lane = tid & 31, w = tid >> 5;
    const int wm = (w & 1) * 64, wn = (w >> 1) * 32;
    const int m0 = blockIdx.y * 128, n0 = blockIdx.x * 128;

    const __nv_bfloat16* Ag[2] = {g_Ahi + (long)m0 * DMODEL, g_Alo + (long)m0 * DMODEL};
    const __nv_bfloat16* Bg[2] = {g_WThi + (long)n0 * DMODEL, g_WTlo + (long)n0 * DMODEL};

    const int lr = tid >> 2;          // 0..63
    const int lc = (tid & 3) * 8;     // elem col of 16B chunk

    float acc[4][4][4] = {};

    // --- stage loader ---
    auto issue = [&](int buf, int k0) {
#pragma unroll
        for (int h = 0; h < 2; h++) {
#pragma unroll
            for (int rep = 0; rep < 2; rep++) {
                int r = lr + rep * 64;
                uint32_t da = (uint32_t)__cvta_generic_to_shared(
                    smem + (buf * 2 + h) * SM_ABUF + r * 40 + lc);
                const void* ga = Ag[h] + (long)r * DMODEL + k0 + lc;
                asm volatile("cp.async.cg.shared.global [%0],[%1],16;\n" ::"r"(da), "l"(ga));
                uint32_t db = (uint32_t)__cvta_generic_to_shared(
                    smem + SM_BBASE + (buf * 2 + h) * SM_ABUF + r * 40 + lc);
                const void* gb = Bg[h] + (long)r * DMODEL + k0 + lc;
                asm volatile("cp.async.cg.shared.global [%0],[%1],16;\n" ::"r"(db), "l"(gb));
            }
        }
        asm volatile("cp.async.commit_group;\n");
    };

    issue(0, 0);
    const int j = lane >> 3, rr = lane & 7;

    for (int kt = 0; kt < 16; kt++) {
        if (kt < 15) {
            issue((kt + 1) & 1, (kt + 1) * 32);
            asm volatile("cp.async.wait_group 1;\n");
        } else {
            asm volatile("cp.async.wait_group 0;\n");
        }
        __syncthreads();
        int buf = kt & 1;
#pragma unroll
        for (int ks = 0; ks < 2; ks++) {
            uint32_t afr[4][2][4];
            uint32_t bfr[4][2][2];
#pragma unroll
            for (int mt = 0; mt < 4; mt++)
#pragma unroll
                for (int h = 0; h < 2; h++) {
                    int row = wm + mt * 16 + rr + (j & 1) * 8;
                    int col = ks * 16 + (j >> 1) * 8;
                    uint32_t addr = (uint32_t)__cvta_generic_to_shared(
                        smem + (buf * 2 + h) * SM_ABUF + row * 40 + col);
                    ldsm4(afr[mt][h], addr);
                }
#pragma unroll
            for (int p = 0; p < 2; p++)
#pragma unroll
                for (int h = 0; h < 2; h++) {
                    int row = wn + p * 16 + rr + (j >> 1) * 8;
                    int col = ks * 16 + (j & 1) * 8;
                    uint32_t addr = (uint32_t)__cvta_generic_to_shared(
                        smem + SM_BBASE + (buf * 2 + h) * SM_ABUF + row * 40 + col);
                    uint32_t t4[4];
                    ldsm4(t4, addr);
                    bfr[2 * p][h][0] = t4[0]; bfr[2 * p][h][1] = t4[1];
                    bfr[2 * p + 1][h][0] = t4[2]; bfr[2 * p + 1][h][1] = t4[3];
                }
#pragma unroll
            for (int mt = 0; mt < 4; mt++)
#pragma unroll
                for (int nt = 0; nt < 4; nt++) {
                    MMA_BF16(acc[mt][nt], afr[mt][0], bfr[nt][0]);  // hi*hi
                    MMA_BF16(acc[mt][nt], afr[mt][0], bfr[nt][1]);  // hi*lo
                    MMA_BF16(acc[mt][nt], afr[mt][1], bfr[nt][0]);  // lo*hi
                }
        }
        __syncthreads();
    }

    // epilogue: write fp32 C
#pragma unroll
    for (int mt = 0; mt < 4; mt++) {
        int row0 = m0 + wm + mt * 16 + (lane >> 2);
#pragma unroll
        for (int nt = 0; nt < 4; nt++) {
            int col0 = n0 + wn + nt * 8 + (lane & 3) * 2;
            float2 v0 = {acc[mt][nt][0], acc[mt][nt][1]};
            float2 v1 = {acc[mt][nt][2], acc[mt][nt][3]};
            *(float2*)(g_qkv + (long)row0 * TD3 + col0) = v0;
            *(float2*)(g_qkv + (long)(row0 + 8) * TD3 + col0) = v1;
        }
    }
}

// ---------------- K2: depthwise k=3 over T + fused norm^2 partials ----------------
__global__ __launch_bounds__(128) void dw3_k(const float* __restrict__ w) {
    int ch = blockIdx.x * 128 + threadIdx.x;   // 0..1535
    int tseg = blockIdx.y;                     // 0..15 (256 t each)
    int b = blockIdx.z;
    int t0 = tseg * 256;
    const float* base = g_qkv + ((long)b * SEQT + t0) * TD3 + ch;
    float* obase = g_qdw + ((long)b * SEQT + t0) * TD3 + ch;
    float w0 = w[ch * 3], w1 = w[ch * 3 + 1], w2 = w[ch * 3 + 2];
    float prev = (t0 > 0) ? base[-TD3] : 0.f;
    float cur = base[0];
    float nacc = 0.f;
#pragma unroll 4
    for (int tt = 0; tt < 256; tt++) {
        int t = t0 + tt;
        float next = (t < SEQT - 1) ? base[(tt + 1) * TD3] : 0.f;
        float o = w0 * prev + w1 * cur + w2 * next;
        obase[tt * TD3] = o;
        if (ch < 1024) nacc += o * o;
        prev = cur; cur = next;
    }
    if (ch < 1024) g_nrmp[(b * 16 + tseg) * 1024 + ch] = nacc;
}

// ---------------- K3: fc over 3H axis -> f (B,T,9,C) ----------------
__global__ __launch_bounds__(256) void fc_k(const float* __restrict__ Wfc,
                                            const float* __restrict__ bfc) {
    __shared__ float s[4][TD3];
    __shared__ float w[24 * 9];
    __shared__ float bb[9];
    int bt0 = blockIdx.x * 4;
    int tid = threadIdx.x;
    if (tid < 216) w[tid] = Wfc[tid];
    if (tid < 9) bb[tid] = bfc[tid];
    const float* src = g_qdw + (long)bt0 * TD3;
    for (int i = tid; i < 4 * TD3; i += 256) s[i / TD3][i % TD3] = src[i];
    __syncthreads();
    for (int o = tid; o < 4 * NF; o += 256) {
        int tt = o / NF, nc = o % NF;
        int n = nc / CHEAD, c = nc % CHEAD;
        float acc = bb[n];
#pragma unroll
        for (int h = 0; h < 24; h++) acc += s[tt][h * CHEAD + c] * w[h * 9 + n];
        g_f[(long)(bt0 + tt) * NF + nc] = acc;
    }
}

// ---------------- K5a: QK^T partials (per t-segment) ----------------
__global__ __launch_bounds__(256) void qk_k() {
    int ts = blockIdx.x & 7;
    int bh = blockIdx.x >> 3;
    int b = bh >> 3, h = bh & 7;
    const float* qbase = g_qdw + (long)b * SEQT * TD3 + h * CHEAD;
    const float* kbase = qbase + DMODEL;
    __shared__ float qs[16][64], ks[16][64];
    int tid = threadIdx.x;
    int cy = tid >> 4, dx = tid & 15;
    float acc[4][4] = {};
    int tstart = ts * 512;
    for (int t0 = tstart; t0 < tstart + 512; t0 += 16) {
        for (int i = tid; i < 1024; i += 256) {
            int tt = i >> 6, cc = i & 63;
            long off = (long)(t0 + tt) * TD3 + cc;
            qs[tt][cc] = qbase[off];
            ks[tt][cc] = kbase[off];
        }
        __syncthreads();
#pragma unroll
        for (int tt = 0; tt < 16; tt++) {
            float ra[4], rb[4];
#pragma unroll
            for (int i = 0; i < 4; i++) ra[i] = qs[tt][cy * 4 + i];
#pragma unroll
            for (int jj = 0; jj < 4; jj++) rb[jj] = ks[tt][dx * 4 + jj];
#pragma unroll
            for (int i = 0; i < 4; i++)
#pragma unroll
                for (int jj = 0; jj < 4; jj++) acc[i][jj] += ra[i] * rb[jj];
        }
        __syncthreads();
    }
    float* dst = g_part + (long)(bh * 8 + ts) * 4096;
#pragma unroll
    for (int i = 0; i < 4; i++)
#pragma unroll
        for (int jj = 0; jj < 4; jj++)
            dst[(cy * 4 + i) * 64 + dx * 4 + jj] = acc[i][jj];
}

// ---------------- K5b: reduce partials + norms + softmax ----------------
__global__ __launch_bounds__(256) void softmax_k(const float* __restrict__ temp) {
    int bh = blockIdx.x;
    int b = bh >> 3, h = bh & 7;
    __shared__ float S[64][64];
    __shared__ float invq[64], invk[64];
    int tid = threadIdx.x;
    for (int i = tid; i < 4096; i += 256) {
        float s = 0.f;
        const float* p = g_part + (long)bh * 8 * 4096 + i;
#pragma unroll
        for (int ts = 0; ts < 8; ts++) s += p[ts * 4096];
        S[i >> 6][i & 63] = s;
    }
    if (tid < 128) {
        int c = tid & 63;
        int off = (tid < 64) ? h * CHEAD + c : DMODEL + h * CHEAD + c;
        float sq = 0.f;
#pragma unroll
        for (int seg = 0; seg < 16; seg++) sq += g_nrmp[(b * 16 + seg) * 1024 + off];
        float inv = 1.f / fmaxf(sqrtf(sq), 1e-12f);
        if (tid < 64) invq[c] = inv; else invk[c] = inv;
    }
    __syncthreads();
    float tmpr = temp[h];
    // softmax: 8 warps, each 8 rows; lane covers cols l and l+32
    int wpid = tid >> 5, lane = tid & 31;
    for (int rr = 0; rr < 8; rr++) {
        int row = wpid * 8 + rr;
        float x0 = S[row][lane] * invq[row] * invk[lane] * tmpr;
        float x1 = S[row][lane + 32] * invq[row] * invk[lane + 32] * tmpr;
        float m = fmaxf(x0, x1);
#pragma unroll
        for (int o = 16; o > 0; o >>= 1) m = fmaxf(m, __shfl_xor_sync(0xffffffffu, m, o));
        float e0 = expf(x0 - m), e1 = expf(x1 - m);
        float s = e0 + e1;
#pragma unroll
        for (int o = 16; o > 0; o >>= 1) s += __shfl_xor_sync(0xffffffffu, s, o);
        float inv = 1.f / s;
        float* dst = g_attn + (bh * 64 + row) * 64;
        dst[lane] = e0 * inv;
        dst[lane + 32] = e1 * inv;
    }
}

// ---------------- K6: regional context (k3 -> relu -> k5), writes out ----------------
__global__ void ctx_k(const float* __restrict__ x, const float* __restrict__ w1,
                      const float* __restrict__ w2, float* __restrict__ out) {
    int idx = blockIdx.x * blockDim.x + threadIdx.x;
    int d = idx % DMODEL;
    int bt = idx / DMODEL;
    int t = bt % SEQT;
    float a0 = w1[d * 3], a1 = w1[d * 3 + 1], a2 = w1[d * 3 + 2];
    const float* xb = x + idx;
    float r[5];
#pragma unroll
    for (int jj = 0; jj < 5; jj++) {
        int tp = t + jj - 2;
        float v = 0.f;
        if (tp >= 0 && tp < SEQT) {
            float xm = (tp > 0) ? xb[(jj - 3) * DMODEL] : 0.f;
            float xc = xb[(jj - 2) * DMODEL];
            float xp = (tp < SEQT - 1) ? xb[(jj - 1) * DMODEL] : 0.f;
            v = fmaxf(a0 * xm + a1 * xc + a2 * xp, 0.f);
        }
        r[jj] = v;
    }
    const float* b2 = w2 + d * 5;
    float acc = 0.f;
#pragma unroll
    for (int jj = 0; jj < 5; jj++) acc += b2[jj] * r[jj];
    out[idx] = acc;
}

// ---------------- K7: grouped conv (fc branch), += out ----------------
__global__ void gconv_k(const float* __restrict__ wd, const float* __restrict__ bd,
                        float* __restrict__ out) {
    int idx = blockIdx.x * blockDim.x + threadIdx.x;
    int d = idx % DMODEL;
    int bt = idx / DMODEL;
    int t = bt % SEQT;
    int g = d >> 3;
    const float* wp = wd + d * 27;
    const float* fb = g_f + (long)bt * NF + g * 9;
    float acc = bd[d];
#pragma unroll
    for (int i = 0; i < 9; i++) {
        float w0 = wp[i * 3], w1 = wp[i * 3 + 1], w2 = wp[i * 3 + 2];
        acc += w1 * fb[i];
        if (t > 0)        acc += w0 * fb[i - NF];
        if (t < SEQT - 1) acc += w2 * fb[i + NF];
    }
    out[idx] += acc;
}

// ---------------- K8: out_att = attn @ V, += out ----------------
__global__ __launch_bounds__(256) void outatt_k(float* __restrict__ out) {
    int tt = blockIdx.x & 63;
    int bh = blockIdx.x >> 6;
    int h = bh & 7, b = bh >> 3;
    __shared__ float A[64][65];
    __shared__ float vs[4][64];
    int tid = threadIdx.x;
    const float* asrc = g_attn + bh * 4096;
    for (int i = tid; i < 4096; i += 256) A[i >> 6][i & 63] = asrc[i];
    int c = tid & 63, tl = tid >> 6;
    int t0 = tt * 64;
    const float* vbase = g_qdw + (long)b * SEQT * TD3 + 2 * DMODEL + h * CHEAD;
    float* obase = out + ((long)b * SEQT + t0) * DMODEL + h * CHEAD;
    __syncthreads();
    for (int ts = 0; ts < 64; ts += 4) {
        vs[tl][c] = vbase[(long)(t0 + ts + tl) * TD3 + c];
        __syncthreads();
        float acc = 0.f;
#pragma unroll
        for (int d = 0; d < 64; d++) acc += A[c][d] * vs[tl][d];
        obase[(long)(ts + tl) * DMODEL + c] += acc;
        __syncthreads();
    }
}

// ---------------- launch ----------------
extern "C" void kernel_launch(void* const* d_in, const int* in_sizes, int n_in,
                              void* d_out, int out_size) {
    const float* x       = (const float*)d_in[0];
    const float* W_qkv   = (const float*)d_in[1];
    const float* w_qkvdw = (const float*)d_in[2];
    const float* w_ctx1  = (const float*)d_in[3];
    const float* w_ctx2  = (const float*)d_in[4];
    const float* W_fc    = (const float*)d_in[5];
    const float* b_fc    = (const float*)d_in[6];
    const float* w_dep   = (const float*)d_in[7];
    const float* b_dep   = (const float*)d_in[8];
    const float* temp    = (const float*)d_in[9];
    float* out = (float*)d_out;

    cudaFuncSetAttribute(gemm_k, cudaFuncAttributeMaxDynamicSharedMemorySize, 81920);

    convA_k<<<(MTOT * DMODEL / 4) / 256, 256>>>(x);
    convW_k<<<(DMODEL * TD3) / 256, 256>>>(W_qkv);
    gemm_k<<<dim3(TD3 / 128, MTOT / 128), 256, 81920>>>();
    dw3_k<<<dim3(12, 16, BATCH), 128>>>(w_qkvdw);
    fc_k<<<MTOT / 4, 256>>>(W_fc, b_fc);
    qk_k<<<BATCH * NHEADS * 8, 256>>>();
    softmax_k<<<BATCH * NHEADS, 256>>>(temp);
    ctx_k<<<(MTOT * DMODEL) / 256, 256>>>(x, w_ctx1, w_ctx2, out);
    gconv_k<<<(MTOT * DMODEL) / 256, 256>>>(w_dep, b_dep, out);
    outatt_k<<<BATCH * NHEADS * (SEQT / 64), 256>>>(out);
}

// round 5
// speedup vs baseline: 2.0610x; 1.0941x over previous
#include <cuda_runtime.h>
#include <cuda_bf16.h>
#include <cstdint>

#define BATCH 8
#define SEQT 4096
#define DMODEL 512
#define NHEADS 8
#define CHEAD 64
#define TD3 1536      // 3*D
#define NF 576        // 9*C
#define MTOT (BATCH * SEQT)   // 32768

// ---------------- scratch (device globals; allocation-free) ----------------
__device__ float g_qkv[(long)MTOT * TD3];           // 201 MB (post-GEMM)
__device__ float g_qdw[(long)MTOT * TD3];           // 201 MB (post depthwise)
__device__ float g_f[(long)MTOT * NF];              // 75 MB
__device__ float g_attn[BATCH * NHEADS * CHEAD * CHEAD];
__device__ float g_part[BATCH * NHEADS * 8 * CHEAD * CHEAD];
__device__ float g_nrmp[BATCH * 32 * 1024];         // norm^2 partials (32 t-segments)
__device__ __nv_bfloat16 g_Ahi[(long)MTOT * DMODEL];
__device__ __nv_bfloat16 g_Alo[(long)MTOT * DMODEL];
__device__ __nv_bfloat16 g_WThi[TD3 * DMODEL];      // transposed W (N,K)
__device__ __nv_bfloat16 g_WTlo[TD3 * DMODEL];

// ---------------- convert x -> bf16 hi/lo ----------------
__global__ void convA_k(const float* __restrict__ x) {
    int i = blockIdx.x * blockDim.x + threadIdx.x;
    float4 v = ((const float4*)x)[i];
    float vv[4] = {v.x, v.y, v.z, v.w};
#pragma unroll
    for (int j = 0; j < 4; j++) {
        __nv_bfloat16 hi = __float2bfloat16_rn(vv[j]);
        __nv_bfloat16 lo = __float2bfloat16_rn(vv[j] - __bfloat162float(hi));
        g_Ahi[(long)i * 4 + j] = hi;
        g_Alo[(long)i * 4 + j] = lo;
    }
}

// ---------------- convert + transpose W -> bf16 hi/lo (N,K) ----------------
__global__ void convW_k(const float* __restrict__ W) {
    int i = blockIdx.x * blockDim.x + threadIdx.x;   // 786432
    int k = i / TD3, n = i % TD3;
    float v = W[i];
    __nv_bfloat16 hi = __float2bfloat16_rn(v);
    __nv_bfloat16 lo = __float2bfloat16_rn(v - __bfloat162float(hi));
    g_WThi[n * DMODEL + k] = hi;
    g_WTlo[n * DMODEL + k] = lo;
}

// ---------------- K1: bf16-split mma.sync GEMM ----------------
// C(32768,1536) = A @ W via Ahi*Bhi + Ahi*Blo + Alo*Bhi, fp32 accum.
// CTA 128x128x32, 8 warps (2x4), warp tile 64x32, mma m16n8k16.
#define SM_ABUF 5120      // elems per (buf,h) plane: 128*40
#define SM_BBASE 20480    // B region start (elems)

__device__ __forceinline__ void ldsm4(uint32_t* r, uint32_t addr) {
    asm volatile("ldmatrix.sync.aligned.m8n8.x4.shared.b16 {%0,%1,%2,%3},[%4];\n"
                 : "=r"(r[0]), "=r"(r[1]), "=r"(r[2]), "=r"(r[3]) : "r"(addr));
}
#define MMA_BF16(c, A, B)                                                          \
    asm volatile(                                                                  \
        "mma.sync.aligned.m16n8k16.row.col.f32.bf16.bf16.f32 "                     \
        "{%0,%1,%2,%3},{%4,%5,%6,%7},{%8,%9},{%0,%1,%2,%3};\n"                     \
        : "+f"(c[0]), "+f"(c[1]), "+f"(c[2]), "+f"(c[3])                           \
        : "r"(A[0]), "r"(A[1]), "r"(A[2]), "r"(A[3]), "r"(B[0]), "r"(B[1]))

__global__ __launch_bounds__(256) void gemm_k() {
    extern __shared__ __align__(16) __nv_bfloat16 smem[];
    const int tid = threadIdx.x;
    const int lane = tid & 31, w = tid >> 5;
    const int wm = (w & 1) * 64, wn = (w >> 1) * 32;
    const int m0 = blockIdx.y * 128, n0 = blockIdx.x * 128;

    const __nv_bfloat16* Ag[2] = {g_Ahi + (long)m0 * DMODEL, g_Alo + (long)m0 * DMODEL};
    const __nv_bfloat16* Bg[2] = {g_WThi + (long)n0 * DMODEL, g_WTlo + (long)n0 * DMODEL};

    const int lr = tid >> 2;          // 0..63
    const int lc = (tid & 3) * 8;     // elem col of 16B chunk

    float acc[4][4][4] = {};

    auto issue = [&](int buf, int k0) {
#pragma unroll
        for (int h = 0; h < 2; h++) {
#pragma unroll
            for (int rep = 0; rep < 2; rep++) {
                int r = lr + rep * 64;
                uint32_t da = (uint32_t)__cvta_generic_to_shared(
                    smem + (buf * 2 + h) * SM_ABUF + r * 40 + lc);
                const void* ga = Ag[h] + (long)r * DMODEL + k0 + lc;
                asm volatile("cp.async.cg.shared.global [%0],[%1],16;\n" ::"r"(da), "l"(ga));
                uint32_t db = (uint32_t)__cvta_generic_to_shared(
                    smem + SM_BBASE + (buf * 2 + h) * SM_ABUF + r * 40 + lc);
                const void* gb = Bg[h] + (long)r * DMODEL + k0 + lc;
                asm volatile("cp.async.cg.shared.global [%0],[%1],16;\n" ::"r"(db), "l"(gb));
            }
        }
        asm volatile("cp.async.commit_group;\n");
    };

    issue(0, 0);
    const int j = lane >> 3, rr = lane & 7;

    for (int kt = 0; kt < 16; kt++) {
        if (kt < 15) {
            issue((kt + 1) & 1, (kt + 1) * 32);
            asm volatile("cp.async.wait_group 1;\n");
        } else {
            asm volatile("cp.async.wait_group 0;\n");
        }
        __syncthreads();
        int buf = kt & 1;
#pragma unroll
        for (int ks = 0; ks < 2; ks++) {
            uint32_t afr[4][2][4];
            uint32_t bfr[4][2][2];
#pragma unroll
            for (int mt = 0; mt < 4; mt++)
#pragma unroll
                for (int h = 0; h < 2; h++) {
                    int row = wm + mt * 16 + rr + (j & 1) * 8;
                    int col = ks * 16 + (j >> 1) * 8;
                    uint32_t addr = (uint32_t)__cvta_generic_to_shared(
                        smem + (buf * 2 + h) * SM_ABUF + row * 40 + col);
                    ldsm4(afr[mt][h], addr);
                }
#pragma unroll
            for (int p = 0; p < 2; p++)
#pragma unroll
                for (int h = 0; h < 2; h++) {
                    int row = wn + p * 16 + rr + (j >> 1) * 8;
                    int col = ks * 16 + (j & 1) * 8;
                    uint32_t addr = (uint32_t)__cvta_generic_to_shared(
                        smem + SM_BBASE + (buf * 2 + h) * SM_ABUF + row * 40 + col);
                    uint32_t t4[4];
                    ldsm4(t4, addr);
                    bfr[2 * p][h][0] = t4[0]; bfr[2 * p][h][1] = t4[1];
                    bfr[2 * p + 1][h][0] = t4[2]; bfr[2 * p + 1][h][1] = t4[3];
                }
#pragma unroll
            for (int mt = 0; mt < 4; mt++)
#pragma unroll
                for (int nt = 0; nt < 4; nt++) {
                    MMA_BF16(acc[mt][nt], afr[mt][0], bfr[nt][0]);  // hi*hi
                    MMA_BF16(acc[mt][nt], afr[mt][0], bfr[nt][1]);  // hi*lo
                    MMA_BF16(acc[mt][nt], afr[mt][1], bfr[nt][0]);  // lo*hi
                }
        }
        __syncthreads();
    }

    // epilogue: write fp32 C
#pragma unroll
    for (int mt = 0; mt < 4; mt++) {
        int row0 = m0 + wm + mt * 16 + (lane >> 2);
#pragma unroll
        for (int nt = 0; nt < 4; nt++) {
            int col0 = n0 + wn + nt * 8 + (lane & 3) * 2;
            float2 v0 = {acc[mt][nt][0], acc[mt][nt][1]};
            float2 v1 = {acc[mt][nt][2], acc[mt][nt][3]};
            *(float2*)(g_qkv + (long)row0 * TD3 + col0) = v0;
            *(float2*)(g_qkv + (long)(row0 + 8) * TD3 + col0) = v1;
        }
    }
}

// ---------------- K2: depthwise k=3 (float4 over channels) + norm^2 partials ----------------
__global__ __launch_bounds__(128) void dw3_k(const float* __restrict__ w) {
    int lane4 = blockIdx.x * 128 + threadIdx.x;   // 0..383 (float4 lane)
    int ch = lane4 * 4;
    int tseg = blockIdx.y;                        // 0..31, 128 t each
    int b = blockIdx.z;
    int t0 = tseg * 128;
    const float4* base = (const float4*)(g_qkv + ((long)b * SEQT + t0) * TD3) + lane4;
    float4* obase = (float4*)(g_qdw + ((long)b * SEQT + t0) * TD3) + lane4;
    float w0[4], w1[4], w2[4];
#pragma unroll
    for (int j = 0; j < 4; j++) {
        w0[j] = w[(ch + j) * 3];
        w1[j] = w[(ch + j) * 3 + 1];
        w2[j] = w[(ch + j) * 3 + 2];
    }
    float4 zero4 = {0.f, 0.f, 0.f, 0.f};
    float4 prev = (t0 > 0) ? base[-384] : zero4;
    float4 cur = base[0];
    float4 nacc = zero4;
#pragma unroll 8
    for (int tt = 0; tt < 128; tt++) {
        int t = t0 + tt;
        float4 next = (t < SEQT - 1) ? base[(tt + 1) * 384] : zero4;
        float4 o;
        o.x = w0[0] * prev.x + w1[0] * cur.x + w2[0] * next.x;
        o.y = w0[1] * prev.y + w1[1] * cur.y + w2[1] * next.y;
        o.z = w0[2] * prev.z + w1[2] * cur.z + w2[2] * next.z;
        o.w = w0[3] * prev.w + w1[3] * cur.w + w2[3] * next.w;
        obase[tt * 384] = o;
        nacc.x += o.x * o.x; nacc.y += o.y * o.y;
        nacc.z += o.z * o.z; nacc.w += o.w * o.w;
        prev = cur; cur = next;
    }
    if (ch < 1024)
        ((float4*)(g_nrmp + ((b * 32 + tseg) << 10)))[lane4] = nacc;
}

// ---------------- K3: fc over 3H axis -> f (B,T,9,C) ----------------
__global__ __launch_bounds__(256) void fc_k(const float* __restrict__ Wfc,
                                            const float* __restrict__ bfc) {
    __shared__ float s[4][TD3];
    __shared__ float w[24 * 9];
    __shared__ float bb[9];
    int bt0 = blockIdx.x * 4;
    int tid = threadIdx.x;
    if (tid < 216) w[tid] = Wfc[tid];
    if (tid < 9) bb[tid] = bfc[tid];
    const float4* src = (const float4*)(g_qdw + (long)bt0 * TD3);
    for (int i = tid; i < TD3; i += 256)
        ((float4*)&s[0][0])[i] = src[i];
    __syncthreads();
    for (int o = tid; o < 4 * NF; o += 256) {
        int tt = o / NF, nc = o % NF;
        int n = nc / CHEAD, c = nc % CHEAD;
        float acc = bb[n];
#pragma unroll
        for (int h = 0; h < 24; h++) acc += s[tt][h * CHEAD + c] * w[h * 9 + n];
        g_f[(long)(bt0 + tt) * NF + nc] = acc;
    }
}

// ---------------- K5a: QK^T partials (per t-segment) ----------------
__global__ __launch_bounds__(256) void qk_k() {
    int ts = blockIdx.x & 7;
    int bh = blockIdx.x >> 3;
    int b = bh >> 3, h = bh & 7;
    const float* qbase = g_qdw + (long)b * SEQT * TD3 + h * CHEAD;
    const float* kbase = qbase + DMODEL;
    __shared__ float qs[16][64], ks[16][64];
    int tid = threadIdx.x;
    int cy = tid >> 4, dx = tid & 15;
    float acc[4][4] = {};
    int tstart = ts * 512;
    for (int t0 = tstart; t0 < tstart + 512; t0 += 16) {
        {
            int tt = tid >> 4, cc4 = tid & 15;
            long off = (long)(t0 + tt) * TD3 + cc4 * 4;
            *(float4*)&qs[tt][cc4 * 4] = *(const float4*)(qbase + off);
            *(float4*)&ks[tt][cc4 * 4] = *(const float4*)(kbase + off);
        }
        __syncthreads();
#pragma unroll
        for (int tt = 0; tt < 16; tt++) {
            float4 ra = *(float4*)&qs[tt][cy * 4];
            float4 rb = *(float4*)&ks[tt][dx * 4];
            float a4[4] = {ra.x, ra.y, ra.z, ra.w};
            float b4[4] = {rb.x, rb.y, rb.z, rb.w};
#pragma unroll
            for (int i = 0; i < 4; i++)
#pragma unroll
                for (int jj = 0; jj < 4; jj++) acc[i][jj] += a4[i] * b4[jj];
        }
        __syncthreads();
    }
    float* dst = g_part + (long)(bh * 8 + ts) * 4096;
#pragma unroll
    for (int i = 0; i < 4; i++)
#pragma unroll
        for (int jj = 0; jj < 4; jj++)
            dst[(cy * 4 + i) * 64 + dx * 4 + jj] = acc[i][jj];
}

// ---------------- K5b: reduce partials + norms + softmax ----------------
__global__ __launch_bounds__(256) void softmax_k(const float* __restrict__ temp) {
    int bh = blockIdx.x;
    int b = bh >> 3, h = bh & 7;
    __shared__ float S[64][64];
    __shared__ float invq[64], invk[64];
    int tid = threadIdx.x;
    for (int i = tid; i < 4096; i += 256) {
        float s = 0.f;
        const float* p = g_part + (long)bh * 8 * 4096 + i;
#pragma unroll
        for (int ts = 0; ts < 8; ts++) s += p[ts * 4096];
        S[i >> 6][i & 63] = s;
    }
    if (tid < 128) {
        int c = tid & 63;
        int off = (tid < 64) ? h * CHEAD + c : DMODEL + h * CHEAD + c;
        float sq = 0.f;
#pragma unroll
        for (int seg = 0; seg < 32; seg++) sq += g_nrmp[((b * 32 + seg) << 10) + off];
        float inv = 1.f / fmaxf(sqrtf(sq), 1e-12f);
        if (tid < 64) invq[c] = inv; else invk[c] = inv;
    }
    __syncthreads();
    float tmpr = temp[h];
    int wpid = tid >> 5, lane = tid & 31;
    for (int rr = 0; rr < 8; rr++) {
        int row = wpid * 8 + rr;
        float x0 = S[row][lane] * invq[row] * invk[lane] * tmpr;
        float x1 = S[row][lane + 32] * invq[row] * invk[lane + 32] * tmpr;
        float m = fmaxf(x0, x1);
#pragma unroll
        for (int o = 16; o > 0; o >>= 1) m = fmaxf(m, __shfl_xor_sync(0xffffffffu, m, o));
        float e0 = expf(x0 - m), e1 = expf(x1 - m);
        float s = e0 + e1;
#pragma unroll
        for (int o = 16; o > 0; o >>= 1) s += __shfl_xor_sync(0xffffffffu, s, o);
        float inv = 1.f / s;
        float* dst = g_attn + (bh * 64 + row) * 64;
        dst[lane] = e0 * inv;
        dst[lane + 32] = e1 * inv;
    }
}

// ---------------- K6: fused ctx (k3->relu->k5) + grouped conv, writes out ----------------
__global__ void cg_k(const float* __restrict__ x, const float* __restrict__ w1,
                     const float* __restrict__ w2, const float* __restrict__ wd,
                     const float* __restrict__ bd, float* __restrict__ out) {
    int idx = blockIdx.x * blockDim.x + threadIdx.x;
    int d = idx % DMODEL;
    int bt = idx / DMODEL;
    int t = bt % SEQT;
    // --- ctx branch ---
    float a0 = w1[d * 3], a1 = w1[d * 3 + 1], a2 = w1[d * 3 + 2];
    const float* xb = x + idx;
    float r[5];
#pragma unroll
    for (int jj = 0; jj < 5; jj++) {
        int tp = t + jj - 2;
        float v = 0.f;
        if (tp >= 0 && tp < SEQT) {
            float xm = (tp > 0) ? xb[(jj - 3) * DMODEL] : 0.f;
            float xc = xb[(jj - 2) * DMODEL];
            float xp = (tp < SEQT - 1) ? xb[(jj - 1) * DMODEL] : 0.f;
            v = fmaxf(a0 * xm + a1 * xc + a2 * xp, 0.f);
        }
        r[jj] = v;
    }
    const float* b2 = w2 + d * 5;
    float acc = 0.f;
#pragma unroll
    for (int jj = 0; jj < 5; jj++) acc += b2[jj] * r[jj];
    // --- grouped conv branch ---
    int g = d >> 3;
    const float* wp = wd + d * 27;
    const float* fb = g_f + (long)bt * NF + g * 9;
    acc += bd[d];
#pragma unroll
    for (int i = 0; i < 9; i++) {
        float v0 = wp[i * 3], v1 = wp[i * 3 + 1], v2 = wp[i * 3 + 2];
        acc += v1 * fb[i];
        if (t > 0)        acc += v0 * fb[i - NF];
        if (t < SEQT - 1) acc += v2 * fb[i + NF];
    }
    out[idx] = acc;
}

// ---------------- K8: out_att = attn @ V, += out ----------------
__global__ __launch_bounds__(256) void outatt_k(float* __restrict__ out) {
    int tt = blockIdx.x & 63;
    int bh = blockIdx.x >> 6;
    int h = bh & 7, b = bh >> 3;
    __shared__ float A[64][65];
    __shared__ float vs[4][64];
    int tid = threadIdx.x;
    const float* asrc = g_attn + bh * 4096;
    for (int i = tid; i < 4096; i += 256) A[i >> 6][i & 63] = asrc[i];
    int c = tid & 63, tl = tid >> 6;
    int t0 = tt * 64;
    const float* vbase = g_qdw + (long)b * SEQT * TD3 + 2 * DMODEL + h * CHEAD;
    float* obase = out + ((long)b * SEQT + t0) * DMODEL + h * CHEAD;
    __syncthreads();
    for (int ts = 0; ts < 64; ts += 4) {
        vs[tl][c] = vbase[(long)(t0 + ts + tl) * TD3 + c];
        __syncthreads();
        float acc = 0.f;
#pragma unroll
        for (int d = 0; d < 64; d++) acc += A[c][d] * vs[tl][d];
        obase[(long)(ts + tl) * DMODEL + c] += acc;
        __syncthreads();
    }
}

// ---------------- launch ----------------
extern "C" void kernel_launch(void* const* d_in, const int* in_sizes, int n_in,
                              void* d_out, int out_size) {
    const float* x       = (const float*)d_in[0];
    const float* W_qkv   = (const float*)d_in[1];
    const float* w_qkvdw = (const float*)d_in[2];
    const float* w_ctx1  = (const float*)d_in[3];
    const float* w_ctx2  = (const float*)d_in[4];
    const float* W_fc    = (const float*)d_in[5];
    const float* b_fc    = (const float*)d_in[6];
    const float* w_dep   = (const float*)d_in[7];
    const float* b_dep   = (const float*)d_in[8];
    const float* temp    = (const float*)d_in[9];
    float* out = (float*)d_out;

    cudaFuncSetAttribute(gemm_k, cudaFuncAttributeMaxDynamicSharedMemorySize, 81920);

    convA_k<<<(MTOT * DMODEL / 4) / 256, 256>>>(x);
    convW_k<<<(DMODEL * TD3) / 256, 256>>>(W_qkv);
    gemm_k<<<dim3(TD3 / 128, MTOT / 128), 256, 81920>>>();
    dw3_k<<<dim3(3, 32, BATCH), 128>>>(w_qkvdw);
    fc_k<<<MTOT / 4, 256>>>(W_fc, b_fc);
    qk_k<<<BATCH * NHEADS * 8, 256>>>();
    softmax_k<<<BATCH * NHEADS, 256>>>(temp);
    cg_k<<<(MTOT * DMODEL) / 256, 256>>>(x, w_ctx1, w_ctx2, w_dep, b_dep, out);
    outatt_k<<<BATCH * NHEADS * (SEQT / 64), 256>>>(out);
}

// round 7
// speedup vs baseline: 2.3199x; 1.1257x over previous
#include <cuda_runtime.h>
#include <cuda_fp16.h>
#include <cstdint>

#define BATCH 8
#define SEQT 4096
#define DMODEL 512
#define NHEADS 8
#define CHEAD 64
#define TD3 1536      // 3*D
#define NF 576        // 9*C
#define MTOT (BATCH * SEQT)   // 32768

// ---------------- scratch (device globals; allocation-free) ----------------
__device__ float g_qdw[(long)MTOT * TD3];           // 201 MB (post depthwise)
__device__ float g_f[(long)MTOT * NF];              // 75 MB
__device__ float g_attn[BATCH * NHEADS * CHEAD * CHEAD];
__device__ float g_part[BATCH * NHEADS * 8 * CHEAD * CHEAD];
__device__ float g_nrmp[BATCH * 32 * 1024];         // norm^2 partials (32 t-segments)
__device__ __half g_Af16[(long)MTOT * DMODEL];      // x in fp16
__device__ __half g_Whi[TD3 * DMODEL];              // W^T hi (N,K)
__device__ __half g_Wlo[TD3 * DMODEL];              // W^T lo (N,K)

// ---------------- convert x -> fp16 ----------------
__global__ void convA_k(const float* __restrict__ x) {
    int i = blockIdx.x * blockDim.x + threadIdx.x;   // float4 idx
    float4 v = ((const float4*)x)[i];
    __half2 a = __floats2half2_rn(v.x, v.y);
    __half2 b = __floats2half2_rn(v.z, v.w);
    ((__half2*)g_Af16)[i * 2] = a;
    ((__half2*)g_Af16)[i * 2 + 1] = b;
}

// ---------------- convert + transpose W -> fp16 hi/lo (N,K) ----------------
__global__ void convW_k(const float* __restrict__ W) {
    int i = blockIdx.x * blockDim.x + threadIdx.x;   // 786432
    int k = i / TD3, n = i % TD3;
    float v = W[i];
    __half hi = __float2half_rn(v);
    __half lo = __float2half_rn(v - __half2float(hi));
    g_Whi[n * DMODEL + k] = hi;
    g_Wlo[n * DMODEL + k] = lo;
}

// ---------------- K1: fp16 2-pass GEMM + fused depthwise + norms ----------------
// C(32768,1536) = A @ W via A*Whi + A*Wlo, fp32 accum.
// CTA 128x128x32, 8 warps (2x4), warp tile 64x32, mma m16n8k16.
// Epilogue: C tile -> smem, depthwise k=3 over t (halo rows scalar), write g_qdw.
#define SMP 5120     // elems per plane: 128*40
#define STG 15360    // elems per stage (A | Whi | Wlo)
#define HX_OFF 61440 // byte offset of halo x rows
#define SN_OFF 68640 // byte offset of norm scratch
#define GSMEM 71680

__device__ __forceinline__ void ldsm4(uint32_t* r, uint32_t addr) {
    asm volatile("ldmatrix.sync.aligned.m8n8.x4.shared.b16 {%0,%1,%2,%3},[%4];\n"
                 : "=r"(r[0]), "=r"(r[1]), "=r"(r[2]), "=r"(r[3]) : "r"(addr));
}
#define MMA_F16(c, A, B)                                                           \
    asm volatile(                                                                  \
        "mma.sync.aligned.m16n8k16.row.col.f32.f16.f16.f32 "                       \
        "{%0,%1,%2,%3},{%4,%5,%6,%7},{%8,%9},{%0,%1,%2,%3};\n"                     \
        : "+f"(c[0]), "+f"(c[1]), "+f"(c[2]), "+f"(c[3])                           \
        : "r"(A[0]), "r"(A[1]), "r"(A[2]), "r"(A[3]), "r"(B[0]), "r"(B[1]))

__global__ __launch_bounds__(256) void gemm_k(const float* __restrict__ x,
                                              const float* __restrict__ wdw) {
    extern __shared__ __align__(16) char dsm[];
    __half* smem = (__half*)dsm;
    float* hx = (float*)(dsm + HX_OFF);    // 2 x 512 halo rows of x
    float* Ct = (float*)dsm;               // epilogue: 130 x 132 fp32 (reuse)
    float* sn = (float*)(dsm + SN_OFF);    // 2 x 128 norm partials

    const int tid = threadIdx.x;
    const int lane = tid & 31, w = tid >> 5;
    const int wm = (w & 1) * 64, wn = (w >> 1) * 32;
    const int m0 = blockIdx.y * 128;
    const int n0g = blockIdx.x * 128;
    const int b = m0 >> 12, t0 = m0 & 4095;

    // load halo x rows (zeros when out of batch)
    {
        int hr = tid >> 7, kk = (tid & 127) * 4;
        long mrow = (hr == 0) ? (long)(m0 - 1) : (long)(m0 + 128);
        bool valid = (hr == 0) ? (t0 > 0) : (t0 + 128 < SEQT);
        float4 v = valid ? *(const float4*)(x + mrow * DMODEL + kk)
                         : make_float4(0.f, 0.f, 0.f, 0.f);
        *(float4*)(hx + hr * 512 + kk) = v;
    }

    const __half* gp[3] = {g_Af16 + (long)m0 * DMODEL,
                           g_Whi + (long)n0g * DMODEL,
                           g_Wlo + (long)n0g * DMODEL};

    const int lr = tid >> 2;          // 0..63
    const int lc = (tid & 3) * 8;     // elem col of 16B chunk
    float acc[4][4][4] = {};
    float hacc = 0.f;
    const int hhr = tid >> 7, hn = tid & 127;

    auto issue = [&](int buf, int k0) {
#pragma unroll
        for (int pl = 0; pl < 3; pl++)
#pragma unroll
            for (int rep = 0; rep < 2; rep++) {
                int r = lr + rep * 64;
                uint32_t da = (uint32_t)__cvta_generic_to_shared(
                    smem + buf * STG + pl * SMP + r * 40 + lc);
                const void* ga = gp[pl] + (long)r * DMODEL + k0 + lc;
                asm volatile("cp.async.cg.shared.global [%0],[%1],16;\n"
                             ::"r"(da), "l"(ga));
            }
        asm volatile("cp.async.commit_group;\n");
    };

    issue(0, 0);
    const int j = lane >> 3, rr = lane & 7;

    for (int kt = 0; kt < 16; kt++) {
        if (kt < 15) {
            issue((kt + 1) & 1, (kt + 1) * 32);
            asm volatile("cp.async.wait_group 1;\n");
        } else {
            asm volatile("cp.async.wait_group 0;\n");
        }
        __syncthreads();
        int buf = kt & 1;
        const __half* sb = smem + buf * STG;
        // halo rows: scalar fp32 accumulation using resident W tiles
        {
            const __half* bhp = sb + SMP + hn * 40;
            const __half* blp = sb + 2 * SMP + hn * 40;
            const float* hxp = hx + hhr * 512 + kt * 32;
#pragma unroll
            for (int k2 = 0; k2 < 16; k2++) {
                float2 fh = __half22float2(*(const __half2*)(bhp + k2 * 2));
                float2 fl = __half22float2(*(const __half2*)(blp + k2 * 2));
                hacc += hxp[k2 * 2] * (fh.x + fl.x) + hxp[k2 * 2 + 1] * (fh.y + fl.y);
            }
        }
#pragma unroll
        for (int ks = 0; ks < 2; ks++) {
            uint32_t afr[4][4];
            uint32_t bfr[2][4][2];
#pragma unroll
            for (int mt = 0; mt < 4; mt++) {
                int row = wm + mt * 16 + rr + (j & 1) * 8;
                int col = ks * 16 + (j >> 1) * 8;
                uint32_t addr = (uint32_t)__cvta_generic_to_shared(
                    sb + row * 40 + col);
                ldsm4(afr[mt], addr);
            }
#pragma unroll
            for (int pl = 0; pl < 2; pl++)
#pragma unroll
                for (int p = 0; p < 2; p++) {
                    int row = wn + p * 16 + rr + (j >> 1) * 8;
                    int col = ks * 16 + (j & 1) * 8;
                    uint32_t addr = (uint32_t)__cvta_generic_to_shared(
                        sb + (1 + pl) * SMP + row * 40 + col);
                    uint32_t t4[4];
                    ldsm4(t4, addr);
                    bfr[pl][2 * p][0] = t4[0]; bfr[pl][2 * p][1] = t4[1];
                    bfr[pl][2 * p + 1][0] = t4[2]; bfr[pl][2 * p + 1][1] = t4[3];
                }
#pragma unroll
            for (int mt = 0; mt < 4; mt++)
#pragma unroll
                for (int nt = 0; nt < 4; nt++) {
                    MMA_F16(acc[mt][nt], afr[mt], bfr[0][nt]);  // A * Whi
                    MMA_F16(acc[mt][nt], afr[mt], bfr[1][nt]);  // A * Wlo
                }
        }
        __syncthreads();
    }

    // ---- epilogue: stage C tile in smem (rows 1..128), halo rows 0/129 ----
#pragma unroll
    for (int mt = 0; mt < 4; mt++) {
        int r0 = wm + mt * 16 + (lane >> 2);
#pragma unroll
        for (int nt = 0; nt < 4; nt++) {
            int c0 = wn + nt * 8 + (lane & 3) * 2;
            *(float2*)&Ct[(r0 + 1) * 132 + c0] =
                make_float2(acc[mt][nt][0], acc[mt][nt][1]);
            *(float2*)&Ct[(r0 + 9) * 132 + c0] =
                make_float2(acc[mt][nt][2], acc[mt][nt][3]);
        }
    }
    Ct[(hhr == 0 ? 0 : 129) * 132 + hn] = hacc;
    __syncthreads();

    // ---- depthwise k=3 over t + write g_qdw + norm partials ----
    {
        int c = tid & 127, hr2 = tid >> 7;
        int ch = n0g + c;
        float w0 = wdw[ch * 3], w1 = wdw[ch * 3 + 1], w2 = wdw[ch * 3 + 2];
        int rbase = hr2 * 64;
        float p0 = Ct[rbase * 132 + c];
        float p1 = Ct[(rbase + 1) * 132 + c];
        float* dst = g_qdw + ((long)(b * SEQT + t0 + rbase)) * TD3 + ch;
        float nacc = 0.f;
#pragma unroll 4
        for (int r = 0; r < 64; r++) {
            float p2 = Ct[(rbase + r + 2) * 132 + c];
            float o = w0 * p0 + w1 * p1 + w2 * p2;
            dst[(long)r * TD3] = o;
            nacc += o * o;
            p0 = p1; p1 = p2;
        }
        sn[hr2 * 128 + c] = nacc;
        __syncthreads();
        if (hr2 == 0 && ch < 1024)
            g_nrmp[((b * 32 + (t0 >> 7)) << 10) + ch] = sn[c] + sn[128 + c];
    }
}

// ---------------- K3: fc over 3H axis -> f (B,T,9,C) ----------------
__global__ __launch_bounds__(256) void fc_k(const float* __restrict__ Wfc,
                                            const float* __restrict__ bfc) {
    __shared__ float s[4][TD3];
    __shared__ float w[24 * 9];
    __shared__ float bb[9];
    int bt0 = blockIdx.x * 4;
    int tid = threadIdx.x;
    if (tid < 216) w[tid] = Wfc[tid];
    if (tid < 9) bb[tid] = bfc[tid];
    const float4* src = (const float4*)(g_qdw + (long)bt0 * TD3);
    for (int i = tid; i < TD3; i += 256)
        ((float4*)&s[0][0])[i] = src[i];
    __syncthreads();
    for (int o = tid; o < 4 * NF; o += 256) {
        int tt = o / NF, nc = o % NF;
        int n = nc / CHEAD, c = nc % CHEAD;
        float acc = bb[n];
#pragma unroll
        for (int h = 0; h < 24; h++) acc += s[tt][h * CHEAD + c] * w[h * 9 + n];
        g_f[(long)(bt0 + tt) * NF + nc] = acc;
    }
}

// ---------------- K5a: QK^T partials (per t-segment) ----------------
__global__ __launch_bounds__(256) void qk_k() {
    int ts = blockIdx.x & 7;
    int bh = blockIdx.x >> 3;
    int b = bh >> 3, h = bh & 7;
    const float* qbase = g_qdw + (long)b * SEQT * TD3 + h * CHEAD;
    const float* kbase = qbase + DMODEL;
    __shared__ float qs[16][64], ks[16][64];
    int tid = threadIdx.x;
    int cy = tid >> 4, dx = tid & 15;
    float acc[4][4] = {};
    int tstart = ts * 512;
    for (int t0 = tstart; t0 < tstart + 512; t0 += 16) {
        {
            int tt = tid >> 4, cc4 = tid & 15;
            long off = (long)(t0 + tt) * TD3 + cc4 * 4;
            *(float4*)&qs[tt][cc4 * 4] = *(const float4*)(qbase + off);
            *(float4*)&ks[tt][cc4 * 4] = *(const float4*)(kbase + off);
        }
        __syncthreads();
#pragma unroll
        for (int tt = 0; tt < 16; tt++) {
            float4 ra = *(float4*)&qs[tt][cy * 4];
            float4 rb = *(float4*)&ks[tt][dx * 4];
            float a4[4] = {ra.x, ra.y, ra.z, ra.w};
            float b4[4] = {rb.x, rb.y, rb.z, rb.w};
#pragma unroll
            for (int i = 0; i < 4; i++)
#pragma unroll
                for (int jj = 0; jj < 4; jj++) acc[i][jj] += a4[i] * b4[jj];
        }
        __syncthreads();
    }
    float* dst = g_part + (long)(bh * 8 + ts) * 4096;
#pragma unroll
    for (int i = 0; i < 4; i++)
#pragma unroll
        for (int jj = 0; jj < 4; jj++)
            dst[(cy * 4 + i) * 64 + dx * 4 + jj] = acc[i][jj];
}

// ---------------- K5b: reduce partials + norms + softmax ----------------
__global__ __launch_bounds__(256) void softmax_k(const float* __restrict__ temp) {
    int bh = blockIdx.x;
    int b = bh >> 3, h = bh & 7;
    __shared__ float S[64][64];
    __shared__ float invq[64], invk[64];
    int tid = threadIdx.x;
    for (int i = tid; i < 4096; i += 256) {
        float s = 0.f;
        const float* p = g_part + (long)bh * 8 * 4096 + i;
#pragma unroll
        for (int ts = 0; ts < 8; ts++) s += p[ts * 4096];
        S[i >> 6][i & 63] = s;
    }
    if (tid < 128) {
        int c = tid & 63;
        int off = (tid < 64) ? h * CHEAD + c : DMODEL + h * CHEAD + c;
        float sq = 0.f;
#pragma unroll
        for (int seg = 0; seg < 32; seg++) sq += g_nrmp[((b * 32 + seg) << 10) + off];
        float inv = 1.f / fmaxf(sqrtf(sq), 1e-12f);
        if (tid < 64) invq[c] = inv; else invk[c] = inv;
    }
    __syncthreads();
    float tmpr = temp[h];
    int wpid = tid >> 5, lane = tid & 31;
    for (int rr = 0; rr < 8; rr++) {
        int row = wpid * 8 + rr;
        float x0 = S[row][lane] * invq[row] * invk[lane] * tmpr;
        float x1 = S[row][lane + 32] * invq[row] * invk[lane + 32] * tmpr;
        float m = fmaxf(x0, x1);
#pragma unroll
        for (int o = 16; o > 0; o >>= 1) m = fmaxf(m, __shfl_xor_sync(0xffffffffu, m, o));
        float e0 = expf(x0 - m), e1 = expf(x1 - m);
        float s = e0 + e1;
#pragma unroll
        for (int o = 16; o > 0; o >>= 1) s += __shfl_xor_sync(0xffffffffu, s, o);
        float inv = 1.f / s;
        float* dst = g_attn + (bh * 64 + row) * 64;
        dst[lane] = e0 * inv;
        dst[lane + 32] = e1 * inv;
    }
}

// ---------------- K6: fused ctx (k3->relu->k5) + grouped conv, writes out ----------------
__global__ void cg_k(const float* __restrict__ x, const float* __restrict__ w1,
                     const float* __restrict__ w2, const float* __restrict__ wd,
                     const float* __restrict__ bd, float* __restrict__ out) {
    int idx = blockIdx.x * blockDim.x + threadIdx.x;
    int d = idx % DMODEL;
    int bt = idx / DMODEL;
    int t = bt % SEQT;
    float a0 = w1[d * 3], a1 = w1[d * 3 + 1], a2 = w1[d * 3 + 2];
    const float* xb = x + idx;
    float r[5];
#pragma unroll
    for (int jj = 0; jj < 5; jj++) {
        int tp = t + jj - 2;
        float v = 0.f;
        if (tp >= 0 && tp < SEQT) {
            float xm = (tp > 0) ? xb[(jj - 3) * DMODEL] : 0.f;
            float xc = xb[(jj - 2) * DMODEL];
            float xp = (tp < SEQT - 1) ? xb[(jj - 1) * DMODEL] : 0.f;
            v = fmaxf(a0 * xm + a1 * xc + a2 * xp, 0.f);
        }
        r[jj] = v;
    }
    const float* b2 = w2 + d * 5;
    float acc = 0.f;
#pragma unroll
    for (int jj = 0; jj < 5; jj++) acc += b2[jj] * r[jj];
    int g = d >> 3;
    const float* wp = wd + d * 27;
    const float* fb = g_f + (long)bt * NF + g * 9;
    acc += bd[d];
#pragma unroll
    for (int i = 0; i < 9; i++) {
        float v0 = wp[i * 3], v1 = wp[i * 3 + 1], v2 = wp[i * 3 + 2];
        acc += v1 * fb[i];
        if (t > 0)        acc += v0 * fb[i - NF];
        if (t < SEQT - 1) acc += v2 * fb[i + NF];
    }
    out[idx] = acc;
}

// ---------------- K8: out_att = attn @ V, += out ----------------
__global__ __launch_bounds__(256) void outatt_k(float* __restrict__ out) {
    int tt = blockIdx.x & 63;
    int bh = blockIdx.x >> 6;
    int h = bh & 7, b = bh >> 3;
    __shared__ float A[64][65];
    __shared__ float vs[4][64];
    int tid = threadIdx.x;
    const float* asrc = g_attn + bh * 4096;
    for (int i = tid; i < 4096; i += 256) A[i >> 6][i & 63] = asrc[i];
    int c = tid & 63, tl = tid >> 6;
    int t0 = tt * 64;
    const float* vbase = g_qdw + (long)b * SEQT * TD3 + 2 * DMODEL + h * CHEAD;
    float* obase = out + ((long)b * SEQT + t0) * DMODEL + h * CHEAD;
    __syncthreads();
    for (int ts = 0; ts < 64; ts += 4) {
        vs[tl][c] = vbase[(long)(t0 + ts + tl) * TD3 + c];
        __syncthreads();
        float acc = 0.f;
#pragma unroll
        for (int d = 0; d < 64; d++) acc += A[c][d] * vs[tl][d];
        obase[(long)(ts + tl) * DMODEL + c] += acc;
        __syncthreads();
    }
}

// ---------------- launch ----------------
extern "C" void kernel_launch(void* const* d_in, const int* in_sizes, int n_in,
                              void* d_out, int out_size) {
    const float* x       = (const float*)d_in[0];
    const float* W_qkv   = (const float*)d_in[1];
    const float* w_qkvdw = (const float*)d_in[2];
    const float* w_ctx1  = (const float*)d_in[3];
    const float* w_ctx2  = (const float*)d_in[4];
    const float* W_fc    = (const float*)d_in[5];
    const float* b_fc    = (const float*)d_in[6];
    const float* w_dep   = (const float*)d_in[7];
    const float* b_dep   = (const float*)d_in[8];
    const float* temp    = (const float*)d_in[9];
    float* out = (float*)d_out;

    cudaFuncSetAttribute(gemm_k, cudaFuncAttributeMaxDynamicSharedMemorySize, GSMEM);

    convA_k<<<(MTOT * DMODEL / 4) / 256, 256>>>(x);
    convW_k<<<(DMODEL * TD3) / 256, 256>>>(W_qkv);
    gemm_k<<<dim3(TD3 / 128, MTOT / 128), 256, GSMEM>>>(x, w_qkvdw);
    fc_k<<<MTOT / 4, 256>>>(W_fc, b_fc);
    qk_k<<<BATCH * NHEADS * 8, 256>>>();
    softmax_k<<<BATCH * NHEADS, 256>>>(temp);
    cg_k<<<(MTOT * DMODEL) / 256, 256>>>(x, w_ctx1, w_ctx2, w_dep, b_dep, out);
    outatt_k<<<BATCH * NHEADS * (SEQT / 64), 256>>>(out);
}

// round 16
// speedup vs baseline: 2.5564x; 1.1019x over previous
#include <cuda_runtime.h>
#include <cuda_fp16.h>
#include <cstdint>

#define BATCH 8
#define SEQT 4096
#define DMODEL 512
#define NHEADS 8
#define CHEAD 64
#define TD3 1536      // 3*D
#define NF 576        // 9*C
#define MTOT (BATCH * SEQT)   // 32768

// ---------------- scratch (device globals; allocation-free) ----------------
__device__ float g_qdw[(long)MTOT * TD3];           // 201 MB (post depthwise)
__device__ float g_f[(long)MTOT * NF];              // 75 MB
__device__ float g_attn[BATCH * NHEADS * CHEAD * CHEAD];
__device__ float g_part[BATCH * NHEADS * 8 * CHEAD * CHEAD];
__device__ float g_nrmp[BATCH * 32 * 1024];         // norm^2 partials (32 t-segments)
__device__ __half g_Af16[(long)MTOT * DMODEL];      // x in fp16
__device__ __half g_Whi[TD3 * DMODEL];              // W^T hi (N,K)
__device__ __half g_Wlo[TD3 * DMODEL];              // W^T lo (N,K)

// ---------------- convert x -> fp16 ----------------
__global__ void convA_k(const float* __restrict__ x) {
    int i = blockIdx.x * blockDim.x + threadIdx.x;   // float4 idx
    float4 v = ((const float4*)x)[i];
    __half2 a = __floats2half2_rn(v.x, v.y);
    __half2 b = __floats2half2_rn(v.z, v.w);
    ((__half2*)g_Af16)[i * 2] = a;
    ((__half2*)g_Af16)[i * 2 + 1] = b;
}

// ---------------- convert + transpose W -> fp16 hi/lo (N,K) ----------------
__global__ void convW_k(const float* __restrict__ W) {
    int i = blockIdx.x * blockDim.x + threadIdx.x;   // 786432
    int k = i / TD3, n = i % TD3;
    float v = W[i];
    __half hi = __float2half_rn(v);
    __half lo = __float2half_rn(v - __half2float(hi));
    g_Whi[n * DMODEL + k] = hi;
    g_Wlo[n * DMODEL + k] = lo;
}

// ---------------- K1: fp16 2-pass GEMM + fused depthwise + norms ----------------
#define SMP 5120     // elems per plane: 128*40
#define STG 15360    // elems per stage (A | Whi | Wlo) = 30720 B
#define HX_OFF 92160 // byte offset of halo x rows
#define SN_OFF 96256 // byte offset of norm scratch
#define GSMEM 97280

__device__ __forceinline__ void ldsm4(uint32_t* r, uint32_t addr) {
    asm volatile("ldmatrix.sync.aligned.m8n8.x4.shared.b16 {%0,%1,%2,%3},[%4];\n"
                 : "=r"(r[0]), "=r"(r[1]), "=r"(r[2]), "=r"(r[3]) : "r"(addr));
}
#define MMA_F16(c, A, B)                                                           \
    asm volatile(                                                                  \
        "mma.sync.aligned.m16n8k16.row.col.f32.f16.f16.f32 "                       \
        "{%0,%1,%2,%3},{%4,%5,%6,%7},{%8,%9},{%0,%1,%2,%3};\n"                     \
        : "+f"(c[0]), "+f"(c[1]), "+f"(c[2]), "+f"(c[3])                           \
        : "r"(A[0]), "r"(A[1]), "r"(A[2]), "r"(A[3]), "r"(B[0]), "r"(B[1]))

__global__ __launch_bounds__(256) void gemm_k(const float* __restrict__ x,
                                              const float* __restrict__ wdw) {
    extern __shared__ __align__(16) char dsm[];
    __half* smem = (__half*)dsm;
    float* hx = (float*)(dsm + HX_OFF);    // 2 x 512 halo rows of x
    float* Ct = (float*)dsm;               // epilogue: 130 x 132 fp32 (reuse)
    float* sn = (float*)(dsm + SN_OFF);    // 2 x 128 norm partials

    const int tid = threadIdx.x;
    const int lane = tid & 31, w = tid >> 5;
    const int wm = (w & 1) * 64, wn = (w >> 1) * 32;
    const int m0 = blockIdx.y * 128;
    const int n0g = blockIdx.x * 128;
    const int b = m0 >> 12, t0 = m0 & 4095;

    // load halo x rows (zeros when out of batch)
    {
        int hr = tid >> 7, kk = (tid & 127) * 4;
        long mrow = (hr == 0) ? (long)(m0 - 1) : (long)(m0 + 128);
        bool valid = (hr == 0) ? (t0 > 0) : (t0 + 128 < SEQT);
        float4 v = valid ? *(const float4*)(x + mrow * DMODEL + kk)
                         : make_float4(0.f, 0.f, 0.f, 0.f);
        *(float4*)(hx + hr * 512 + kk) = v;
    }

    const __half* gp[3] = {g_Af16 + (long)m0 * DMODEL,
                           g_Whi + (long)n0g * DMODEL,
                           g_Wlo + (long)n0g * DMODEL};

    const int lr = tid >> 2;          // 0..63
    const int lc = (tid & 3) * 8;     // elem col of 16B chunk
    float acc[4][4][4] = {};
    float hacc = 0.f;
    const int hhr = tid >> 7, hn = tid & 127;

    auto issue = [&](int buf, int k0) {
#pragma unroll
        for (int pl = 0; pl < 3; pl++)
#pragma unroll
            for (int rep = 0; rep < 2; rep++) {
                int r = lr + rep * 64;
                uint32_t da = (uint32_t)__cvta_generic_to_shared(
                    smem + buf * STG + pl * SMP + r * 40 + lc);
                const void* ga = gp[pl] + (long)r * DMODEL + k0 + lc;
                asm volatile("cp.async.cg.shared.global [%0],[%1],16;\n"
                             ::"r"(da), "l"(ga));
            }
        asm volatile("cp.async.commit_group;\n");
    };

    issue(0, 0);
    issue(1, 32);
    issue(2, 64);
    const int j = lane >> 3, rr = lane & 7;

    for (int kt = 0; kt < 16; kt++) {
        if (kt <= 13)      asm volatile("cp.async.wait_group 2;\n");
        else if (kt == 14) asm volatile("cp.async.wait_group 1;\n");
        else               asm volatile("cp.async.wait_group 0;\n");
        __syncthreads();
        int buf = kt % 3;
        const __half* sb = smem + buf * STG;
        // halo rows: scalar fp32 accumulation using resident W tiles
        {
            const __half* bhp = sb + SMP + hn * 40;
            const __half* blp = sb + 2 * SMP + hn * 40;
            const float* hxp = hx + hhr * 512 + kt * 32;
#pragma unroll
            for (int k2 = 0; k2 < 16; k2++) {
                float2 fh = __half22float2(*(const __half2*)(bhp + k2 * 2));
                float2 fl = __half22float2(*(const __half2*)(blp + k2 * 2));
                hacc += hxp[k2 * 2] * (fh.x + fl.x) + hxp[k2 * 2 + 1] * (fh.y + fl.y);
            }
        }
#pragma unroll
        for (int ks = 0; ks < 2; ks++) {
            uint32_t afr[4][4];
            uint32_t bfr[2][4][2];
#pragma unroll
            for (int mt = 0; mt < 4; mt++) {
                int row = wm + mt * 16 + rr + (j & 1) * 8;
                int col = ks * 16 + (j >> 1) * 8;
                uint32_t addr = (uint32_t)__cvta_generic_to_shared(
                    sb + row * 40 + col);
                ldsm4(afr[mt], addr);
            }
#pragma unroll
            for (int pl = 0; pl < 2; pl++)
#pragma unroll
                for (int p = 0; p < 2; p++) {
                    int row = wn + p * 16 + rr + (j >> 1) * 8;
                    int col = ks * 16 + (j & 1) * 8;
                    uint32_t addr = (uint32_t)__cvta_generic_to_shared(
                        sb + (1 + pl) * SMP + row * 40 + col);
                    uint32_t t4[4];
                    ldsm4(t4, addr);
                    bfr[pl][2 * p][0] = t4[0]; bfr[pl][2 * p][1] = t4[1];
                    bfr[pl][2 * p + 1][0] = t4[2]; bfr[pl][2 * p + 1][1] = t4[3];
                }
#pragma unroll
            for (int mt = 0; mt < 4; mt++)
#pragma unroll
                for (int nt = 0; nt < 4; nt++) {
                    MMA_F16(acc[mt][nt], afr[mt], bfr[0][nt]);  // A * Whi
                    MMA_F16(acc[mt][nt], afr[mt], bfr[1][nt]);  // A * Wlo
                }
        }
        __syncthreads();
        if (kt + 3 < 16) issue(buf, (kt + 3) * 32);
    }

    // ---- epilogue: stage C tile in smem (rows 1..128), halo rows 0/129 ----
#pragma unroll
    for (int mt = 0; mt < 4; mt++) {
        int r0 = wm + mt * 16 + (lane >> 2);
#pragma unroll
        for (int nt = 0; nt < 4; nt++) {
            int c0 = wn + nt * 8 + (lane & 3) * 2;
            *(float2*)&Ct[(r0 + 1) * 132 + c0] =
                make_float2(acc[mt][nt][0], acc[mt][nt][1]);
            *(float2*)&Ct[(r0 + 9) * 132 + c0] =
                make_float2(acc[mt][nt][2], acc[mt][nt][3]);
        }
    }
    Ct[(hhr == 0 ? 0 : 129) * 132 + hn] = hacc;
    __syncthreads();

    // ---- depthwise k=3 over t + write g_qdw + norm partials ----
    {
        int c = tid & 127, hr2 = tid >> 7;
        int ch = n0g + c;
        float w0 = wdw[ch * 3], w1 = wdw[ch * 3 + 1], w2 = wdw[ch * 3 + 2];
        int rbase = hr2 * 64;
        float p0 = Ct[rbase * 132 + c];
        float p1 = Ct[(rbase + 1) * 132 + c];
        float* dst = g_qdw + ((long)(b * SEQT + t0 + rbase)) * TD3 + ch;
        float nacc = 0.f;
#pragma unroll 4
        for (int r = 0; r < 64; r++) {
            float p2 = Ct[(rbase + r + 2) * 132 + c];
            float o = w0 * p0 + w1 * p1 + w2 * p2;
            dst[(long)r * TD3] = o;
            nacc += o * o;
            p0 = p1; p1 = p2;
        }
        sn[hr2 * 128 + c] = nacc;
        __syncthreads();
        if (hr2 == 0 && ch < 1024)
            g_nrmp[((b * 32 + (t0 >> 7)) << 10) + ch] = sn[c] + sn[128 + c];
    }
}

// ---------------- K3: fc over 3H axis -> f (register form) ----------------
__global__ __launch_bounds__(256) void fc_k(const float* __restrict__ Wfc,
                                            const float* __restrict__ bfc) {
    __shared__ float w[216];
    __shared__ float bb[9];
    int tid = threadIdx.x;
    if (tid < 216) w[tid] = Wfc[tid];
    if (tid < 9) bb[tid] = bfc[tid];
    __syncthreads();
    int c = tid & 63;
    long bt = (long)blockIdx.x * 4 + (tid >> 6);
    const float* src = g_qdw + bt * TD3 + c;
    float v[24];
#pragma unroll
    for (int h = 0; h < 24; h++) v[h] = src[h * 64];
    float* dst = g_f + bt * NF + c;
#pragma unroll
    for (int n = 0; n < 9; n++) {
        float acc = bb[n];
#pragma unroll
        for (int h = 0; h < 24; h++) acc += v[h] * w[h * 9 + n];
        dst[n * 64] = acc;
    }
}

// ---------------- K5a: QK^T partials (per t-segment) ----------------
__global__ __launch_bounds__(256) void qk_k() {
    int ts = blockIdx.x & 7;
    int bh = blockIdx.x >> 3;
    int b = bh >> 3, h = bh & 7;
    const float* qbase = g_qdw + (long)b * SEQT * TD3 + h * CHEAD;
    const float* kbase = qbase + DMODEL;
    __shared__ float qs[16][64], ks[16][64];
    int tid = threadIdx.x;
    int cy = tid >> 4, dx = tid & 15;
    float acc[4][4] = {};
    int tstart = ts * 512;
    for (int t0 = tstart; t0 < tstart + 512; t0 += 16) {
        {
            int tt = tid >> 4, cc4 = tid & 15;
            long off = (long)(t0 + tt) * TD3 + cc4 * 4;
            *(float4*)&qs[tt][cc4 * 4] = *(const float4*)(qbase + off);
            *(float4*)&ks[tt][cc4 * 4] = *(const float4*)(kbase + off);
        }
        __syncthreads();
#pragma unroll
        for (int tt = 0; tt < 16; tt++) {
            float4 ra = *(float4*)&qs[tt][cy * 4];
            float4 rb = *(float4*)&ks[tt][dx * 4];
            float a4[4] = {ra.x, ra.y, ra.z, ra.w};
            float b4[4] = {rb.x, rb.y, rb.z, rb.w};
#pragma unroll
            for (int i = 0; i < 4; i++)
#pragma unroll
                for (int jj = 0; jj < 4; jj++) acc[i][jj] += a4[i] * b4[jj];
        }
        __syncthreads();
    }
    float* dst = g_part + (long)(bh * 8 + ts) * 4096;
#pragma unroll
    for (int i = 0; i < 4; i++)
#pragma unroll
        for (int jj = 0; jj < 4; jj++)
            dst[(cy * 4 + i) * 64 + dx * 4 + jj] = acc[i][jj];
}

// ---------------- K5b: reduce partials + norms + softmax ----------------
__global__ __launch_bounds__(256) void softmax_k(const float* __restrict__ temp) {
    int bh = blockIdx.x;
    int b = bh >> 3, h = bh & 7;
    __shared__ float S[64][64];
    __shared__ float invq[64], invk[64];
    int tid = threadIdx.x;
    for (int i = tid; i < 4096; i += 256) {
        float s = 0.f;
        const float* p = g_part + (long)bh * 8 * 4096 + i;
#pragma unroll
        for (int ts = 0; ts < 8; ts++) s += p[ts * 4096];
        S[i >> 6][i & 63] = s;
    }
    if (tid < 128) {
        int c = tid & 63;
        int off = (tid < 64) ? h * CHEAD + c : DMODEL + h * CHEAD + c;
        float sq = 0.f;
#pragma unroll
        for (int seg = 0; seg < 32; seg++) sq += g_nrmp[((b * 32 + seg) << 10) + off];
        float inv = 1.f / fmaxf(sqrtf(sq), 1e-12f);
        if (tid < 64) invq[c] = inv; else invk[c] = inv;
    }
    __syncthreads();
    float tmpr = temp[h];
    int wpid = tid >> 5, lane = tid & 31;
    for (int rr = 0; rr < 8; rr++) {
        int row = wpid * 8 + rr;
        float x0 = S[row][lane] * invq[row] * invk[lane] * tmpr;
        float x1 = S[row][lane + 32] * invq[row] * invk[lane + 32] * tmpr;
        float m = fmaxf(x0, x1);
#pragma unroll
        for (int o = 16; o > 0; o >>= 1) m = fmaxf(m, __shfl_xor_sync(0xffffffffu, m, o));
        float e0 = expf(x0 - m), e1 = expf(x1 - m);
        float s = e0 + e1;
#pragma unroll
        for (int o = 16; o > 0; o >>= 1) s += __shfl_xor_sync(0xffffffffu, s, o);
        float inv = 1.f / s;
        float* dst = g_attn + (bh * 64 + row) * 64;
        dst[lane] = e0 * inv;
        dst[lane + 32] = e1 * inv;
    }
}

// ---------------- K6: fused attn@V + ctx + grouped conv -> out (single write) ----------------
__global__ __launch_bounds__(256) void fused_out_k(
    const float* __restrict__ x, const float* __restrict__ w1,
    const float* __restrict__ w2, const float* __restrict__ wd,
    const float* __restrict__ bd, float* __restrict__ out) {
    int tt = blockIdx.x & 63;
    int bh = blockIdx.x >> 6;
    int h = bh & 7, b = bh >> 3;
    __shared__ float A[64][65];
    __shared__ float vs[4][64];
    int tid = threadIdx.x;
    const float* asrc = g_attn + bh * 4096;
    for (int i = tid; i < 4096; i += 256) A[i >> 6][i & 63] = asrc[i];
    int c = tid & 63, tl = tid >> 6;
    int t0 = tt * 64;
    int d = h * CHEAD + c;
    // hoisted per-channel weights (constant across this thread's 16 t's)
    float a0 = w1[d * 3], a1 = w1[d * 3 + 1], a2 = w1[d * 3 + 2];
    float bw[5];
#pragma unroll
    for (int jj = 0; jj < 5; jj++) bw[jj] = w2[d * 5 + jj];
    float wpv[27];
#pragma unroll
    for (int i = 0; i < 27; i++) wpv[i] = wd[d * 27 + i];
    float bdv = bd[d];
    int g = d >> 3;
    const float* vbase = g_qdw + (long)b * SEQT * TD3 + 2 * DMODEL + h * CHEAD;
    float* obase = out + ((long)b * SEQT + t0) * DMODEL + h * CHEAD;
    __syncthreads();
    for (int ts = 0; ts < 64; ts += 4) {
        vs[tl][c] = vbase[(long)(t0 + ts + tl) * TD3 + c];
        __syncthreads();
        // attention part
        float acc = 0.f;
#pragma unroll
        for (int dd = 0; dd < 64; dd++) acc += A[c][dd] * vs[tl][dd];
        // ctx part (k3 -> relu -> k5), verbatim from cg_k
        int t = t0 + ts + tl;
        int idx = (b * SEQT + t) * DMODEL + d;
        const float* xb = x + idx;
        float r[5];
#pragma unroll
        for (int jj = 0; jj < 5; jj++) {
            int tp = t + jj - 2;
            float v = 0.f;
            if (tp >= 0 && tp < SEQT) {
                float xm = (tp > 0) ? xb[(jj - 3) * DMODEL] : 0.f;
                float xc = xb[(jj - 2) * DMODEL];
                float xp = (tp < SEQT - 1) ? xb[(jj - 1) * DMODEL] : 0.f;
                v = fmaxf(a0 * xm + a1 * xc + a2 * xp, 0.f);
            }
            r[jj] = v;
        }
#pragma unroll
        for (int jj = 0; jj < 5; jj++) acc += bw[jj] * r[jj];
        // grouped conv part, verbatim from cg_k (weights hoisted)
        const float* fb = g_f + (long)(b * SEQT + t) * NF + g * 9;
        acc += bdv;
#pragma unroll
        for (int i = 0; i < 9; i++) {
            acc += wpv[i * 3 + 1] * fb[i];
            if (t > 0)        acc += wpv[i * 3] * fb[i - NF];
            if (t < SEQT - 1) acc += wpv[i * 3 + 2] * fb[i + NF];
        }
        obase[(long)(ts + tl) * DMODEL + c] = acc;
        __syncthreads();
    }
}

// ---------------- launch ----------------
extern "C" void kernel_launch(void* const* d_in, const int* in_sizes, int n_in,
                              void* d_out, int out_size) {
    const float* x       = (const float*)d_in[0];
    const float* W_qkv   = (const float*)d_in[1];
    const float* w_qkvdw = (const float*)d_in[2];
    const float* w_ctx1  = (const float*)d_in[3];
    const float* w_ctx2  = (const float*)d_in[4];
    const float* W_fc    = (const float*)d_in[5];
    const float* b_fc    = (const float*)d_in[6];
    const float* w_dep   = (const float*)d_in[7];
    const float* b_dep   = (const float*)d_in[8];
    const float* temp    = (const float*)d_in[9];
    float* out = (float*)d_out;

    cudaFuncSetAttribute(gemm_k, cudaFuncAttributeMaxDynamicSharedMemorySize, GSMEM);

    convA_k<<<(MTOT * DMODEL / 4) / 256, 256>>>(x);
    convW_k<<<(DMODEL * TD3) / 256, 256>>>(W_qkv);
    gemm_k<<<dim3(TD3 / 128, MTOT / 128), 256, GSMEM>>>(x, w_qkvdw);
    fc_k<<<MTOT / 4, 256>>>(W_fc, b_fc);
    qk_k<<<BATCH * NHEADS * 8, 256>>>();
    softmax_k<<<BATCH * NHEADS, 256>>>(temp);
    fused_out_k<<<BATCH * NHEADS * (SEQT / 64), 256>>>(x, w_ctx1, w_ctx2,
                                                       w_dep, b_dep, out);
}